// round 14
// baseline (speedup 1.0000x reference)
#include <cuda_runtime.h>
#include <math.h>

#define Nn 50000
#define Ee 800000
#define Hh 64
#define Ll 2048
#define NBLK 196   /* ceil(Nn/256) */

/* ---------------- device scratch (no allocs allowed) ---------------- */
__device__ float g_xw[Nn * Hh];
__device__ float g_z[Nn * Hh];
__device__ float g_deg[Nn];
__device__ float g_dinv[Nn];
__device__ int   g_mask[Nn];
__device__ float g_pre0[Ll * 256];
__device__ float g_hfinal[Hh];
__device__ float g_logits[Nn];
__device__ float g_pL[NBLK];
__device__ float g_pY[NBLK];
__device__ int   g_pI[NBLK];
__device__ float g_pS[NBLK];
__device__ float g_lmax;
__device__ float g_sum;
__device__ int   g_next;

__device__ __forceinline__ float sigf(float x) { return 1.0f / (1.0f + expf(-x)); }

/* Threefry-2x32, key (k0,k1). 20 rounds, key injection every 4. */
__device__ __forceinline__ void threefry2x32(unsigned k0, unsigned k1,
                                             unsigned& x0, unsigned& x1) {
    unsigned ks2 = k0 ^ k1 ^ 0x1BD11BDAu;
#define TF_R4(a,b,c,d) \
    x0 += x1; x1 = __funnelshift_l(x1, x1, (a)); x1 ^= x0; \
    x0 += x1; x1 = __funnelshift_l(x1, x1, (b)); x1 ^= x0; \
    x0 += x1; x1 = __funnelshift_l(x1, x1, (c)); x1 ^= x0; \
    x0 += x1; x1 = __funnelshift_l(x1, x1, (d)); x1 ^= x0;
    x0 += k0;  x1 += k1;
    TF_R4(13,15,26,6);  x0 += k1;  x1 += ks2 + 1u;
    TF_R4(17,29,16,24); x0 += ks2; x1 += k0  + 2u;
    TF_R4(13,15,26,6);  x0 += k0;  x1 += k1  + 3u;
    TF_R4(17,29,16,24); x0 += k1;  x1 += ks2 + 4u;
    TF_R4(13,15,26,6);  x0 += ks2; x1 += k0  + 5u;
#undef TF_R4
}

/* ---------------- kernels ---------------- */
__global__ void k_zero() {
    int i = blockIdx.x * blockDim.x + threadIdx.x;
    int stride = gridDim.x * blockDim.x;
    for (int j = i; j < Nn * Hh; j += stride) g_z[j] = 0.f;
    for (int j = i; j < Nn; j += stride) { g_deg[j] = 0.f; g_mask[j] = 0; }
}

__global__ void k_setup(const int* ei, const float* ew, const int* visited) {
    int i = blockIdx.x * blockDim.x + threadIdx.x;
    if (i < Ee) {
        atomicAdd(&g_deg[ei[Ee + i]], ew[i]);         /* incoming edge weight */
    } else if (i < Ee + Nn) {
        atomicAdd(&g_deg[i - Ee], 1.0f);              /* self loop */
    } else if (i < Ee + Nn + Ll) {
        g_mask[visited[i - Ee - Nn]] = 1;
    }
}

__global__ void k_xw(const float* __restrict__ x, const float* __restrict__ W1) {
    int j = threadIdx.x & 63;
    int r = blockIdx.x * 4 + (threadIdx.x >> 6);
    if (r >= Nn) return;
    float acc = 0.f;
#pragma unroll 16
    for (int k = 0; k < 64; k++) acc += x[r * 64 + k] * W1[k * 64 + j];
    g_xw[r * 64 + j] = acc;
}

__global__ void k_dinv() {
    int n = blockIdx.x * 256 + threadIdx.x;
    if (n < Nn) { float d = g_deg[n]; g_dinv[n] = (d > 0.f) ? 1.0f / sqrtf(d) : 0.f; }
}

__global__ void k_scatter(const int* __restrict__ ei, const float* __restrict__ ew) {
    long long idx = (long long)blockIdx.x * 256 + threadIdx.x;
    if (idx >= (long long)Ee * 16) return;
    int e = (int)(idx >> 4), q = (int)(idx & 15);
    int s = ei[e], d = ei[Ee + e];
    float norm = g_dinv[s] * ew[e] * g_dinv[d];
    float4 v = ((const float4*)g_xw)[s * 16 + q];
    float* zp = &g_z[d * 64 + q * 4];
    atomicAdd(zp + 0, norm * v.x);
    atomicAdd(zp + 1, norm * v.y);
    atomicAdd(zp + 2, norm * v.z);
    atomicAdd(zp + 3, norm * v.w);
}

__global__ void k_fin(const float* __restrict__ b1) {
    int idx = blockIdx.x * 256 + threadIdx.x;
    if (idx >= Nn * 16) return;
    int n = idx >> 4, q = idx & 15;
    float di = g_dinv[n];
    float c = di * di;                       /* self-loop norm (weight 1) */
    float4 v = ((const float4*)g_xw)[idx];
    float4 z = ((float4*)g_z)[idx];
    float4 b = ((const float4*)b1)[q];
    z.x += c * v.x + b.x;
    z.y += c * v.y + b.y;
    z.z += c * v.z + b.z;
    z.w += c * v.w + b.w;
    ((float4*)g_z)[idx] = z;
}

__global__ void k_pre0(const float* __restrict__ Wih0, const float* __restrict__ bih0,
                       const float* __restrict__ bhh0, const int* __restrict__ visited) {
    __shared__ __align__(16) float seq[64];
    int t = blockIdx.x, g = threadIdx.x;
    if (g < 64) seq[g] = g_z[visited[t] * 64 + g];
    __syncthreads();
    float acc = bih0[g] + bhh0[g];
    const float4* w = (const float4*)(Wih0 + g * 64);
    const float4* h4 = (const float4*)seq;
#pragma unroll
    for (int j = 0; j < 16; j++) {
        float4 wv = w[j]; float4 hv = h4[j];
        acc += wv.x * hv.x + wv.y * hv.y + wv.z * hv.z + wv.w * hv.w;
    }
    g_pre0[t * 256 + g] = acc;
}

__global__ void __launch_bounds__(256, 1)
k_lstm(const float* __restrict__ Whh0, const float* __restrict__ Wih1,
       const float* __restrict__ Whh1, const float* __restrict__ bih1,
       const float* __restrict__ bhh1) {
    int g = threadIdx.x;
    float w0[64], wi1[64], wh1[64];
    {
        const float4* p0 = (const float4*)(Whh0 + g * 64);
        const float4* p1 = (const float4*)(Wih1 + g * 64);
        const float4* p2 = (const float4*)(Whh1 + g * 64);
#pragma unroll
        for (int j = 0; j < 16; j++) {
            float4 a = p0[j]; w0[4*j]=a.x;  w0[4*j+1]=a.y;  w0[4*j+2]=a.z;  w0[4*j+3]=a.w;
            float4 b = p1[j]; wi1[4*j]=b.x; wi1[4*j+1]=b.y; wi1[4*j+2]=b.z; wi1[4*j+3]=b.w;
            float4 c = p2[j]; wh1[4*j]=c.x; wh1[4*j+1]=c.y; wh1[4*j+2]=c.z; wh1[4*j+3]=c.w;
        }
    }
    float bias1 = bih1[g] + bhh1[g];
    __shared__ __align__(16) float h0[64];
    __shared__ __align__(16) float h1[64];
    __shared__ float gates[256];
    float c0 = 0.f, c1 = 0.f;
    if (g < 64) { h0[g] = 0.f; h1[g] = 0.f; }
    __syncthreads();
    for (int t = 0; t < Ll; t++) {
        /* layer 0: gates = pre0[t] + Whh0 @ h0 */
        float acc = g_pre0[t * 256 + g];
        const float4* ha = (const float4*)h0;
#pragma unroll
        for (int j = 0; j < 16; j++) {
            float4 hv = ha[j];
            acc += w0[4*j]*hv.x + w0[4*j+1]*hv.y + w0[4*j+2]*hv.z + w0[4*j+3]*hv.w;
        }
        gates[g] = acc;
        __syncthreads();
        if (g < 64) {
            float i = sigf(gates[g]), f = sigf(gates[64+g]);
            float gg = tanhf(gates[128+g]), o = sigf(gates[192+g]);
            c0 = f * c0 + i * gg;
            h0[g] = o * tanhf(c0);
        }
        __syncthreads();
        /* layer 1: gates = b1 + Wih1 @ h0(new) + Whh1 @ h1(old) */
        acc = bias1;
        const float4* hb = (const float4*)h0;
        const float4* hc = (const float4*)h1;
#pragma unroll
        for (int j = 0; j < 16; j++) {
            float4 a = hb[j]; float4 b = hc[j];
            acc += wi1[4*j]*a.x + wi1[4*j+1]*a.y + wi1[4*j+2]*a.z + wi1[4*j+3]*a.w
                 + wh1[4*j]*b.x + wh1[4*j+1]*b.y + wh1[4*j+2]*b.z + wh1[4*j+3]*b.w;
        }
        gates[g] = acc;
        __syncthreads();
        if (g < 64) {
            float i = sigf(gates[g]), f = sigf(gates[64+g]);
            float gg = tanhf(gates[128+g]), o = sigf(gates[192+g]);
            c1 = f * c1 + i * gg;
            h1[g] = o * tanhf(c1);
        }
        __syncthreads();
    }
    if (g < 64) g_hfinal[g] = h1[g];
}

__global__ void k_logits() {
    __shared__ __align__(16) float hf[64];
    __shared__ float sL[256], sY[256];
    __shared__ int sI[256];
    int t = threadIdx.x;
    int n = blockIdx.x * 256 + t;
    if (t < 64) hf[t] = g_hfinal[t];
    __syncthreads();
    float L = -INFINITY, Y = -INFINITY;
    int I = (n < Nn) ? n : 0x7fffffff;
    if (n < Nn) {
        float acc = 0.f;
        const float4* z4 = (const float4*)(g_z + n * 64);
        const float4* h4 = (const float4*)hf;
#pragma unroll
        for (int j = 0; j < 16; j++) {
            float4 a = z4[j]; float4 b = h4[j];
            acc += a.x*b.x + a.y*b.y + a.z*b.z + a.w*b.w;
        }
        L = g_mask[n] ? -INFINITY : acc;
        g_logits[n] = L;
        /* gumbel via threefry, key(1)=(0,1), partitionable counter x=(0,n), bits=out0^out1 */
        unsigned x0 = 0u, x1 = (unsigned)n;
        threefry2x32(0u, 1u, x0, x1);
        unsigned bits = x0 ^ x1;
        float f = __uint_as_float((bits >> 9) | 0x3f800000u) - 1.0f;
        const float tiny = 1.1754944e-38f;
        float u = fmaxf(tiny, f * (1.0f - tiny) + tiny);
        float gum = -logf(-logf(u));
        Y = L + gum;
    }
    sL[t] = L; sY[t] = Y; sI[t] = I;
    __syncthreads();
    for (int s = 128; s > 0; s >>= 1) {
        if (t < s) {
            sL[t] = fmaxf(sL[t], sL[t + s]);
            float y2 = sY[t + s]; int i2 = sI[t + s];
            if (y2 > sY[t] || (y2 == sY[t] && i2 < sI[t])) { sY[t] = y2; sI[t] = i2; }
        }
        __syncthreads();
    }
    if (t == 0) { g_pL[blockIdx.x] = sL[0]; g_pY[blockIdx.x] = sY[0]; g_pI[blockIdx.x] = sI[0]; }
}

__global__ void k_red1() {
    __shared__ float sL[256], sY[256];
    __shared__ int sI[256];
    int t = threadIdx.x;
    sL[t] = (t < NBLK) ? g_pL[t] : -INFINITY;
    sY[t] = (t < NBLK) ? g_pY[t] : -INFINITY;
    sI[t] = (t < NBLK) ? g_pI[t] : 0x7fffffff;
    __syncthreads();
    for (int s = 128; s > 0; s >>= 1) {
        if (t < s) {
            sL[t] = fmaxf(sL[t], sL[t + s]);
            float y2 = sY[t + s]; int i2 = sI[t + s];
            if (y2 > sY[t] || (y2 == sY[t] && i2 < sI[t])) { sY[t] = y2; sI[t] = i2; }
        }
        __syncthreads();
    }
    if (t == 0) { g_lmax = sL[0]; g_next = sI[0]; }
}

__global__ void k_esum() {
    __shared__ float sm[256];
    int t = threadIdx.x;
    int n = blockIdx.x * 256 + t;
    float e = 0.f;
    if (n < Nn) e = expf(g_logits[n] - g_lmax);   /* exp(-inf - lmax) = 0 for masked */
    sm[t] = e;
    __syncthreads();
    for (int s2 = 128; s2 > 0; s2 >>= 1) {
        if (t < s2) sm[t] += sm[t + s2];
        __syncthreads();
    }
    if (t == 0) g_pS[blockIdx.x] = sm[0];
}

__global__ void k_red2(float* out, int off) {
    __shared__ float sm[256];
    int t = threadIdx.x;
    sm[t] = (t < NBLK) ? g_pS[t] : 0.f;
    __syncthreads();
    for (int s2 = 128; s2 > 0; s2 >>= 1) {
        if (t < s2) sm[t] += sm[t + s2];
        __syncthreads();
    }
    if (t == 0) {
        g_sum = sm[0];
        if (off > 0) out[0] = (float)g_next;   /* tuple order: (next_node, probs) */
    }
}

__global__ void k_probs(float* out, int off) {
    int n = blockIdx.x * 256 + threadIdx.x;
    if (n < Nn) out[off + n] = expf(g_logits[n] - g_lmax) / g_sum;
}

/* ---------------- launcher ---------------- */
extern "C" void kernel_launch(void* const* d_in, const int* in_sizes, int n_in,
                              void* d_out, int out_size) {
    const float* x       = (const float*)d_in[0];
    const int*   ei      = (const int*)d_in[1];
    const float* ew      = (const float*)d_in[2];
    const int*   visited = (const int*)d_in[3];
    const float* W1      = (const float*)d_in[4];
    const float* b1      = (const float*)d_in[5];
    const float* Wih0    = (const float*)d_in[6];
    const float* Whh0    = (const float*)d_in[7];
    const float* bih0    = (const float*)d_in[8];
    const float* bhh0    = (const float*)d_in[9];
    const float* Wih1    = (const float*)d_in[10];
    const float* Whh1    = (const float*)d_in[11];
    const float* bih1    = (const float*)d_in[12];
    const float* bhh1    = (const float*)d_in[13];
    float* out = (float*)d_out;
    int off = (out_size > Nn) ? (out_size - Nn) : 0;  /* expect 1 (next_node scalar) */

    k_zero<<<2048, 256>>>();
    k_setup<<<(Ee + Nn + Ll + 255) / 256, 256>>>(ei, ew, visited);
    k_xw<<<(Nn + 3) / 4, 256>>>(x, W1);
    k_dinv<<<NBLK, 256>>>();
    k_scatter<<<(Ee * 16 + 255) / 256, 256>>>(ei, ew);
    k_fin<<<(Nn * 16 + 255) / 256, 256>>>(b1);
    k_pre0<<<Ll, 256>>>(Wih0, bih0, bhh0, visited);
    k_lstm<<<1, 256>>>(Whh0, Wih1, Whh1, bih1, bhh1);
    k_logits<<<NBLK, 256>>>();
    k_red1<<<1, 256>>>();
    k_esum<<<NBLK, 256>>>();
    k_red2<<<1, 256>>>(out, off);
    k_probs<<<NBLK, 256>>>(out, off);
}

// round 15
// speedup vs baseline: 1.6229x; 1.6229x over previous
#include <cuda_runtime.h>
#include <math.h>

#define Nn 50000
#define Ee 800000
#define Hh 64
#define Ll 2048
#define NBLK 196   /* ceil(Nn/256) */

/* ---------------- device scratch (no allocs allowed) ---------------- */
__device__ float g_xw[Nn * Hh];
__device__ float g_z[Nn * Hh];
__device__ float g_deg[Nn];
__device__ float g_dinv[Nn];
__device__ int   g_mask[Nn];
__device__ float g_pre0[(Ll + 1) * 256];   /* extra row so prefetch can read unconditionally */
__device__ float g_hfinal[Hh];
__device__ float g_logits[Nn];
__device__ float g_pL[NBLK];
__device__ float g_pY[NBLK];
__device__ int   g_pI[NBLK];
__device__ float g_pS[NBLK];
__device__ float g_lmax;
__device__ float g_sum;
__device__ int   g_next;

typedef unsigned long long ull;

/* packed f32x2 helpers (FFMA2 only reachable via PTX fma.rn.f32x2) */
#define FMA2(acc, w, h) asm("fma.rn.f32x2 %0, %1, %2, %0;" : "+l"(acc) : "l"(w), "l"(h))
__device__ __forceinline__ ull pk2(float a, float b) {
    ull r; asm("mov.b64 %0, {%1, %2};" : "=l"(r) : "f"(a), "f"(b)); return r;
}
__device__ __forceinline__ float sum2(ull v) {
    float a, b; asm("mov.b64 {%0, %1}, %2;" : "=f"(a), "=f"(b) : "l"(v)); return a + b;
}

/* fast activations: __expf = ex2.approx based, rel err ~2e-7 */
__device__ __forceinline__ float fsig(float x) {
    return __fdividef(1.0f, 1.0f + __expf(-x));
}
__device__ __forceinline__ float ftan(float x) {
    float xc = fminf(fmaxf(x, -15.0f), 15.0f);
    float e = __expf(2.0f * xc);
    return __fdividef(e - 1.0f, e + 1.0f);
}

/* Threefry-2x32, key (k0,k1). 20 rounds, key injection every 4. */
__device__ __forceinline__ void threefry2x32(unsigned k0, unsigned k1,
                                             unsigned& x0, unsigned& x1) {
    unsigned ks2 = k0 ^ k1 ^ 0x1BD11BDAu;
#define TF_R4(a,b,c,d) \
    x0 += x1; x1 = __funnelshift_l(x1, x1, (a)); x1 ^= x0; \
    x0 += x1; x1 = __funnelshift_l(x1, x1, (b)); x1 ^= x0; \
    x0 += x1; x1 = __funnelshift_l(x1, x1, (c)); x1 ^= x0; \
    x0 += x1; x1 = __funnelshift_l(x1, x1, (d)); x1 ^= x0;
    x0 += k0;  x1 += k1;
    TF_R4(13,15,26,6);  x0 += k1;  x1 += ks2 + 1u;
    TF_R4(17,29,16,24); x0 += ks2; x1 += k0  + 2u;
    TF_R4(13,15,26,6);  x0 += k0;  x1 += k1  + 3u;
    TF_R4(17,29,16,24); x0 += k1;  x1 += ks2 + 4u;
    TF_R4(13,15,26,6);  x0 += ks2; x1 += k0  + 5u;
#undef TF_R4
}

/* ---------------- kernels ---------------- */
__global__ void k_zero() {
    int i = blockIdx.x * blockDim.x + threadIdx.x;
    int stride = gridDim.x * blockDim.x;
    for (int j = i; j < Nn * Hh; j += stride) g_z[j] = 0.f;
    for (int j = i; j < Nn; j += stride) { g_deg[j] = 0.f; g_mask[j] = 0; }
}

__global__ void k_setup(const int* ei, const float* ew, const int* visited) {
    int i = blockIdx.x * blockDim.x + threadIdx.x;
    if (i < Ee) {
        atomicAdd(&g_deg[ei[Ee + i]], ew[i]);         /* incoming edge weight */
    } else if (i < Ee + Nn) {
        atomicAdd(&g_deg[i - Ee], 1.0f);              /* self loop */
    } else if (i < Ee + Nn + Ll) {
        g_mask[visited[i - Ee - Nn]] = 1;
    }
}

__global__ void k_xw(const float* __restrict__ x, const float* __restrict__ W1) {
    int j = threadIdx.x & 63;
    int r = blockIdx.x * 4 + (threadIdx.x >> 6);
    if (r >= Nn) return;
    float acc = 0.f;
#pragma unroll 16
    for (int k = 0; k < 64; k++) acc += x[r * 64 + k] * W1[k * 64 + j];
    g_xw[r * 64 + j] = acc;
}

__global__ void k_dinv() {
    int n = blockIdx.x * 256 + threadIdx.x;
    if (n < Nn) { float d = g_deg[n]; g_dinv[n] = (d > 0.f) ? 1.0f / sqrtf(d) : 0.f; }
}

/* 4 threads per edge, each issuing 4x red.global.add.v4.f32 (16 floats) */
__global__ void k_scatter(const int* __restrict__ ei, const float* __restrict__ ew) {
    int idx = blockIdx.x * 256 + threadIdx.x;
    if (idx >= Ee * 4) return;
    int e = idx >> 2, part = idx & 3;
    int s = ei[e], d = ei[Ee + e];
    float norm = g_dinv[s] * ew[e] * g_dinv[d];
    const float4* xp = (const float4*)(g_xw + s * 64) + part * 4;
    float* zp = g_z + d * 64 + part * 16;
#pragma unroll
    for (int q = 0; q < 4; q++) {
        float4 v = xp[q];
        asm volatile("red.global.add.v4.f32 [%0], {%1, %2, %3, %4};"
                     :: "l"(zp + 4 * q),
                        "f"(norm * v.x), "f"(norm * v.y),
                        "f"(norm * v.z), "f"(norm * v.w) : "memory");
    }
}

__global__ void k_fin(const float* __restrict__ b1) {
    int idx = blockIdx.x * 256 + threadIdx.x;
    if (idx >= Nn * 16) return;
    int n = idx >> 4, q = idx & 15;
    float di = g_dinv[n];
    float c = di * di;                       /* self-loop norm (weight 1) */
    float4 v = ((const float4*)g_xw)[idx];
    float4 z = ((float4*)g_z)[idx];
    float4 b = ((const float4*)b1)[q];
    z.x += c * v.x + b.x;
    z.y += c * v.y + b.y;
    z.z += c * v.z + b.z;
    z.w += c * v.w + b.w;
    ((float4*)g_z)[idx] = z;
}

__global__ void k_pre0(const float* __restrict__ Wih0, const float* __restrict__ bih0,
                       const float* __restrict__ bhh0, const int* __restrict__ visited) {
    __shared__ __align__(16) float seq[64];
    int t = blockIdx.x, g = threadIdx.x;
    if (g < 64) seq[g] = g_z[visited[t] * 64 + g];
    __syncthreads();
    float acc = bih0[g] + bhh0[g];
    const float4* w = (const float4*)(Wih0 + g * 64);
    const float4* h4 = (const float4*)seq;
#pragma unroll
    for (int j = 0; j < 16; j++) {
        float4 wv = w[j]; float4 hv = h4[j];
        acc += wv.x * hv.x + wv.y * hv.y + wv.z * hv.z + wv.w * hv.w;
    }
    g_pre0[t * 256 + g] = acc;
}

__global__ void __launch_bounds__(256, 1)
k_lstm(const float* __restrict__ Whh0, const float* __restrict__ Wih1,
       const float* __restrict__ Whh1, const float* __restrict__ bih1,
       const float* __restrict__ bhh1) {
    int g = threadIdx.x;
    /* recurrent weights packed into f32x2 registers: 96 ull = 192 regs */
    ull w0[32], wi1[32], wh1[32];
    {
        const ulonglong2* p0 = (const ulonglong2*)(Whh0 + g * 64);
        const ulonglong2* p1 = (const ulonglong2*)(Wih1 + g * 64);
        const ulonglong2* p2 = (const ulonglong2*)(Whh1 + g * 64);
#pragma unroll
        for (int j = 0; j < 16; j++) {
            ulonglong2 a = p0[j]; w0[2*j]  = a.x; w0[2*j+1]  = a.y;
            ulonglong2 b = p1[j]; wi1[2*j] = b.x; wi1[2*j+1] = b.y;
            ulonglong2 c = p2[j]; wh1[2*j] = c.x; wh1[2*j+1] = c.y;
        }
    }
    float bias1 = bih1[g] + bhh1[g];
    __shared__ __align__(16) float h0s[64];
    __shared__ __align__(16) float h1s[64];
    __shared__ float gates[256];
    float c0 = 0.f, c1 = 0.f;
    if (g < 64) { h0s[g] = 0.f; h1s[g] = 0.f; }
    float pnext = g_pre0[g];
    __syncthreads();
    const ull* H0 = (const ull*)h0s;
    const ull* H1 = (const ull*)h1s;
    for (int t = 0; t < Ll; t++) {
        float p = pnext;
        pnext = g_pre0[(t + 1) * 256 + g];          /* prefetch next step (extra row exists) */
        /* segment A: acc0 = pre0 + Whh0 @ h0_old ; acc1 = bias1 + Whh1 @ h1_old */
        ull acc0 = pk2(p, 0.0f);
        ull acc1 = pk2(bias1, 0.0f);
#pragma unroll
        for (int k = 0; k < 32; k++) {
            ull ha = H0[k]; ull hb = H1[k];
            FMA2(acc0, w0[k], ha);
            FMA2(acc1, wh1[k], hb);
        }
        gates[g] = sum2(acc0);
        __syncthreads();
        if (g < 64) {
            float i = fsig(gates[g]), f = fsig(gates[64 + g]);
            float gg = ftan(gates[128 + g]), o = fsig(gates[192 + g]);
            c0 = f * c0 + i * gg;
            h0s[g] = o * ftan(c0);
        }
        __syncthreads();
        /* segment B: acc1 += Wih1 @ h0_new */
#pragma unroll
        for (int k = 0; k < 32; k++) {
            ull ha = H0[k];
            FMA2(acc1, wi1[k], ha);
        }
        gates[g] = sum2(acc1);
        __syncthreads();
        if (g < 64) {
            float i = fsig(gates[g]), f = fsig(gates[64 + g]);
            float gg = ftan(gates[128 + g]), o = fsig(gates[192 + g]);
            c1 = f * c1 + i * gg;
            h1s[g] = o * ftan(c1);
        }
        __syncthreads();
    }
    if (g < 64) g_hfinal[g] = h1s[g];
}

__global__ void k_logits() {
    __shared__ __align__(16) float hf[64];
    __shared__ float sL[256], sY[256];
    __shared__ int sI[256];
    int t = threadIdx.x;
    int n = blockIdx.x * 256 + t;
    if (t < 64) hf[t] = g_hfinal[t];
    __syncthreads();
    float L = -INFINITY, Y = -INFINITY;
    int I = (n < Nn) ? n : 0x7fffffff;
    if (n < Nn) {
        float acc = 0.f;
        const float4* z4 = (const float4*)(g_z + n * 64);
        const float4* h4 = (const float4*)hf;
#pragma unroll
        for (int j = 0; j < 16; j++) {
            float4 a = z4[j]; float4 b = h4[j];
            acc += a.x*b.x + a.y*b.y + a.z*b.z + a.w*b.w;
        }
        L = g_mask[n] ? -INFINITY : acc;
        g_logits[n] = L;
        /* gumbel via threefry, key(1)=(0,1), partitionable counter x=(0,n), bits=out0^out1 */
        unsigned x0 = 0u, x1 = (unsigned)n;
        threefry2x32(0u, 1u, x0, x1);
        unsigned bits = x0 ^ x1;
        float f = __uint_as_float((bits >> 9) | 0x3f800000u) - 1.0f;
        const float tiny = 1.1754944e-38f;
        float u = fmaxf(tiny, f * (1.0f - tiny) + tiny);
        float gum = -logf(-logf(u));
        Y = L + gum;
    }
    sL[t] = L; sY[t] = Y; sI[t] = I;
    __syncthreads();
    for (int s = 128; s > 0; s >>= 1) {
        if (t < s) {
            sL[t] = fmaxf(sL[t], sL[t + s]);
            float y2 = sY[t + s]; int i2 = sI[t + s];
            if (y2 > sY[t] || (y2 == sY[t] && i2 < sI[t])) { sY[t] = y2; sI[t] = i2; }
        }
        __syncthreads();
    }
    if (t == 0) { g_pL[blockIdx.x] = sL[0]; g_pY[blockIdx.x] = sY[0]; g_pI[blockIdx.x] = sI[0]; }
}

__global__ void k_red1() {
    __shared__ float sL[256], sY[256];
    __shared__ int sI[256];
    int t = threadIdx.x;
    sL[t] = (t < NBLK) ? g_pL[t] : -INFINITY;
    sY[t] = (t < NBLK) ? g_pY[t] : -INFINITY;
    sI[t] = (t < NBLK) ? g_pI[t] : 0x7fffffff;
    __syncthreads();
    for (int s = 128; s > 0; s >>= 1) {
        if (t < s) {
            sL[t] = fmaxf(sL[t], sL[t + s]);
            float y2 = sY[t + s]; int i2 = sI[t + s];
            if (y2 > sY[t] || (y2 == sY[t] && i2 < sI[t])) { sY[t] = y2; sI[t] = i2; }
        }
        __syncthreads();
    }
    if (t == 0) { g_lmax = sL[0]; g_next = sI[0]; }
}

__global__ void k_esum() {
    __shared__ float sm[256];
    int t = threadIdx.x;
    int n = blockIdx.x * 256 + t;
    float e = 0.f;
    if (n < Nn) e = expf(g_logits[n] - g_lmax);   /* exp(-inf - lmax) = 0 for masked */
    sm[t] = e;
    __syncthreads();
    for (int s2 = 128; s2 > 0; s2 >>= 1) {
        if (t < s2) sm[t] += sm[t + s2];
        __syncthreads();
    }
    if (t == 0) g_pS[blockIdx.x] = sm[0];
}

__global__ void k_red2(float* out, int off) {
    __shared__ float sm[256];
    int t = threadIdx.x;
    sm[t] = (t < NBLK) ? g_pS[t] : 0.f;
    __syncthreads();
    for (int s2 = 128; s2 > 0; s2 >>= 1) {
        if (t < s2) sm[t] += sm[t + s2];
        __syncthreads();
    }
    if (t == 0) {
        g_sum = sm[0];
        if (off > 0) out[0] = (float)g_next;   /* tuple order: (next_node, probs) */
    }
}

__global__ void k_probs(float* out, int off) {
    int n = blockIdx.x * 256 + threadIdx.x;
    if (n < Nn) out[off + n] = expf(g_logits[n] - g_lmax) / g_sum;
}

/* ---------------- launcher ---------------- */
extern "C" void kernel_launch(void* const* d_in, const int* in_sizes, int n_in,
                              void* d_out, int out_size) {
    const float* x       = (const float*)d_in[0];
    const int*   ei      = (const int*)d_in[1];
    const float* ew      = (const float*)d_in[2];
    const int*   visited = (const int*)d_in[3];
    const float* W1      = (const float*)d_in[4];
    const float* b1      = (const float*)d_in[5];
    const float* Wih0    = (const float*)d_in[6];
    const float* Whh0    = (const float*)d_in[7];
    const float* bih0    = (const float*)d_in[8];
    const float* bhh0    = (const float*)d_in[9];
    const float* Wih1    = (const float*)d_in[10];
    const float* Whh1    = (const float*)d_in[11];
    const float* bih1    = (const float*)d_in[12];
    const float* bhh1    = (const float*)d_in[13];
    float* out = (float*)d_out;
    int off = (out_size > Nn) ? (out_size - Nn) : 0;  /* expect 1 (next_node scalar) */

    k_zero<<<2048, 256>>>();
    k_setup<<<(Ee + Nn + Ll + 255) / 256, 256>>>(ei, ew, visited);
    k_xw<<<(Nn + 3) / 4, 256>>>(x, W1);
    k_dinv<<<NBLK, 256>>>();
    k_scatter<<<(Ee * 4 + 255) / 256, 256>>>(ei, ew);
    k_fin<<<(Nn * 16 + 255) / 256, 256>>>(b1);
    k_pre0<<<Ll, 256>>>(Wih0, bih0, bhh0, visited);
    k_lstm<<<1, 256>>>(Whh0, Wih1, Whh1, bih1, bhh1);
    k_logits<<<NBLK, 256>>>();
    k_red1<<<1, 256>>>();
    k_esum<<<NBLK, 256>>>();
    k_red2<<<1, 256>>>(out, off);
    k_probs<<<NBLK, 256>>>(out, off);
}